// round 7
// baseline (speedup 1.0000x reference)
#include <cuda_runtime.h>

#define B_ 4096
#define N_ 64
#define H_ 256
#define TB3 16
#define BQ_ 1024          // batch quarter
#define NB_GQ 80          // 16 b-tiles x 5 m-tiles per quarter (64x64)
#define NB_UV 2048

typedef unsigned long long u64;

// Scratch (allocation-free rule: __device__ globals)
__device__ float g_UV[N_ * H_];     //  64 KiB
__device__ float g_sW[B_ * H_];     //   4 MiB
__device__ float g_gate[B_ * N_];   //   1 MiB

// ---------- packed fp32x2 helpers (sm_103a FFMA2) ----------
__device__ __forceinline__ u64 pack2(float x, float y) {
    u64 r; asm("mov.b64 %0, {%1, %2};" : "=l"(r) : "f"(x), "f"(y)); return r;
}
__device__ __forceinline__ u64 fma2(u64 a, u64 b, u64 c) {
    u64 d; asm("fma.rn.f32x2 %0, %1, %2, %3;" : "=l"(d) : "l"(a), "l"(b), "l"(c)); return d;
}
__device__ __forceinline__ float2 unpack2(u64 v) {
    float2 r; asm("mov.b64 {%0, %1}, %2;" : "=f"(r.x), "=f"(r.y) : "l"(v)); return r;
}

// ---------------------------------------------------------------------------
// Producer kernel for one batch quarter:
//  blocks [0, 80):  GEMM  C[b,m] = s_t[b,:].M[m,:], M = concat(W_w, h+w)
//    b in [bq*1024, bq*1024+1024). 64x64 tiles, Kc=32, k-major smem,
//    4b x 4m micro via f32x2 packed FMA.  m<256 -> g_sW ; mx==4 -> g_gate.
//  blocks [80, ...): UV[n,k] = sum_h h.U + w.V  (only present when bq==0)
// ---------------------------------------------------------------------------
__global__ void __launch_bounds__(256) k12q(
    const float* __restrict__ s, const float* __restrict__ W,
    const float* __restrict__ h, const float* __restrict__ w,
    const float* __restrict__ U, const float* __restrict__ V,
    const int bq)
{
    __shared__ float sa[32][64];   // [k][b_local]
    __shared__ float sb[32][64];   // [k][m_local]
    const int tid = threadIdx.x;
    const int blk = blockIdx.x;

    if (blk < NB_GQ) {
        const int mx = blk % 5;
        const int b0 = bq * BQ_ + (blk / 5) * 64;
        const int m0 = mx * 64;
        const bool gate_tile = (mx == 4);

        const int row = tid & 63;
        const int kq = (tid >> 6) << 2;    // 0,4,8,12
        const int tx = tid & 15;
        const int ty = tid >> 4;
        const int rb = ty << 2;            // b micro base (4 rows, as 2 pairs)
        const int cm = tx << 2;            // m micro base (4 cols)

        u64 acc2[2][4] = {};

        float4 ra0, ra1, rb0, rb1;
        ra0 = *(const float4*)&s[(b0 + row) * H_ + kq];
        ra1 = *(const float4*)&s[(b0 + row) * H_ + 16 + kq];
        if (!gate_tile) {
            rb0 = *(const float4*)&W[(m0 + row) * H_ + kq];
            rb1 = *(const float4*)&W[(m0 + row) * H_ + 16 + kq];
        } else {
            float4 x0 = *(const float4*)&h[row * H_ + kq];
            float4 x1 = *(const float4*)&h[row * H_ + 16 + kq];
            float4 y0 = *(const float4*)&w[row * H_ + kq];
            float4 y1 = *(const float4*)&w[row * H_ + 16 + kq];
            rb0 = make_float4(x0.x + y0.x, x0.y + y0.y, x0.z + y0.z, x0.w + y0.w);
            rb1 = make_float4(x1.x + y1.x, x1.y + y1.y, x1.z + y1.z, x1.w + y1.w);
        }

        for (int kc = 0; kc < H_; kc += 32) {
            sa[kq + 0][row] = ra0.x; sa[kq + 1][row] = ra0.y;
            sa[kq + 2][row] = ra0.z; sa[kq + 3][row] = ra0.w;
            sa[16 + kq + 0][row] = ra1.x; sa[16 + kq + 1][row] = ra1.y;
            sa[16 + kq + 2][row] = ra1.z; sa[16 + kq + 3][row] = ra1.w;
            sb[kq + 0][row] = rb0.x; sb[kq + 1][row] = rb0.y;
            sb[kq + 2][row] = rb0.z; sb[kq + 3][row] = rb0.w;
            sb[16 + kq + 0][row] = rb1.x; sb[16 + kq + 1][row] = rb1.y;
            sb[16 + kq + 2][row] = rb1.z; sb[16 + kq + 3][row] = rb1.w;
            __syncthreads();

            if (kc + 32 < H_) {
                const int kn = kc + 32;
                ra0 = *(const float4*)&s[(b0 + row) * H_ + kn + kq];
                ra1 = *(const float4*)&s[(b0 + row) * H_ + kn + 16 + kq];
                if (!gate_tile) {
                    rb0 = *(const float4*)&W[(m0 + row) * H_ + kn + kq];
                    rb1 = *(const float4*)&W[(m0 + row) * H_ + kn + 16 + kq];
                } else {
                    float4 x0 = *(const float4*)&h[row * H_ + kn + kq];
                    float4 x1 = *(const float4*)&h[row * H_ + kn + 16 + kq];
                    float4 y0 = *(const float4*)&w[row * H_ + kn + kq];
                    float4 y1 = *(const float4*)&w[row * H_ + kn + 16 + kq];
                    rb0 = make_float4(x0.x + y0.x, x0.y + y0.y, x0.z + y0.z, x0.w + y0.w);
                    rb1 = make_float4(x1.x + y1.x, x1.y + y1.y, x1.z + y1.z, x1.w + y1.w);
                }
            }

#pragma unroll 8
            for (int k = 0; k < 32; ++k) {
                const ulonglong2 a2 = *(const ulonglong2*)&sa[k][rb];
                const float4 bv = *(const float4*)&sb[k][cm];
                u64 bx = pack2(bv.x, bv.x);
                u64 by = pack2(bv.y, bv.y);
                u64 bz = pack2(bv.z, bv.z);
                u64 bw = pack2(bv.w, bv.w);
                acc2[0][0] = fma2(a2.x, bx, acc2[0][0]);
                acc2[0][1] = fma2(a2.x, by, acc2[0][1]);
                acc2[0][2] = fma2(a2.x, bz, acc2[0][2]);
                acc2[0][3] = fma2(a2.x, bw, acc2[0][3]);
                acc2[1][0] = fma2(a2.y, bx, acc2[1][0]);
                acc2[1][1] = fma2(a2.y, by, acc2[1][1]);
                acc2[1][2] = fma2(a2.y, bz, acc2[1][2]);
                acc2[1][3] = fma2(a2.y, bw, acc2[1][3]);
            }
            __syncthreads();
        }

#pragma unroll
        for (int ib = 0; ib < 2; ++ib) {
            float2 c0 = unpack2(acc2[ib][0]);
            float2 c1 = unpack2(acc2[ib][1]);
            float2 c2 = unpack2(acc2[ib][2]);
            float2 c3 = unpack2(acc2[ib][3]);
            const int bA = b0 + rb + 2 * ib;
            if (!gate_tile) {
                *(float4*)&g_sW[bA * H_ + m0 + cm] = make_float4(c0.x, c1.x, c2.x, c3.x);
                *(float4*)&g_sW[(bA + 1) * H_ + m0 + cm] = make_float4(c0.y, c1.y, c2.y, c3.y);
            } else {
                *(float4*)&g_gate[bA * N_ + cm] = make_float4(
                    1.0f / (1.0f + __expf(-c0.x)), 1.0f / (1.0f + __expf(-c1.x)),
                    1.0f / (1.0f + __expf(-c2.x)), 1.0f / (1.0f + __expf(-c3.x)));
                *(float4*)&g_gate[(bA + 1) * N_ + cm] = make_float4(
                    1.0f / (1.0f + __expf(-c0.y)), 1.0f / (1.0f + __expf(-c1.y)),
                    1.0f / (1.0f + __expf(-c2.y)), 1.0f / (1.0f + __expf(-c3.y)));
            }
        }
    } else {
        // ---------------- UV part (bq==0 only): warp per output element ----
        const int id = blk - NB_GQ;
        const int n = id >> 5;
        const int kg = id & 31;
        const int warp = tid >> 5;
        const int lane = tid & 31;
        const int k = kg * 8 + warp;
        const int off = lane * 8;

        const float4* u4 = (const float4*)(U + k * H_ + off);
        const float4* v4 = (const float4*)(V + k * H_ + off);
        const float4* h4 = (const float4*)(h + n * H_ + off);
        const float4* w4 = (const float4*)(w + n * H_ + off);
        float4 u0 = u4[0], u1 = u4[1];
        float4 v0 = v4[0], v1 = v4[1];
        float4 x0 = __ldg(h4), x1 = __ldg(h4 + 1);
        float4 y0 = __ldg(w4), y1 = __ldg(w4 + 1);

        float acc = 0.f;
        acc = fmaf(u0.x, x0.x, acc); acc = fmaf(u0.y, x0.y, acc);
        acc = fmaf(u0.z, x0.z, acc); acc = fmaf(u0.w, x0.w, acc);
        acc = fmaf(u1.x, x1.x, acc); acc = fmaf(u1.y, x1.y, acc);
        acc = fmaf(u1.z, x1.z, acc); acc = fmaf(u1.w, x1.w, acc);
        acc = fmaf(v0.x, y0.x, acc); acc = fmaf(v0.y, y0.y, acc);
        acc = fmaf(v0.z, y0.z, acc); acc = fmaf(v0.w, y0.w, acc);
        acc = fmaf(v1.x, y1.x, acc); acc = fmaf(v1.y, y1.y, acc);
        acc = fmaf(v1.z, y1.z, acc); acc = fmaf(v1.w, y1.w, acc);

#pragma unroll
        for (int offm = 16; offm > 0; offm >>= 1)
            acc += __shfl_xor_sync(0xFFFFFFFFu, acc, offm);
        if (lane == 0) g_UV[n * H_ + k] = acc;
    }
}

// ---------------------------------------------------------------------------
// Consumer kernel for one batch quarter (R2 body, best measured):
// out[b,n,:] = normalize( h[n,:] + g[b,n]*prelu(UV[n,:] + sW[b,:]) )
// grid = (4 n-tiles, 64 b-tiles of TB3=16), block = 256
// ---------------------------------------------------------------------------
__device__ __forceinline__ void row_step(const float4 uv, const float4 hh,
                                         const float4 sw, const float g,
                                         const float a, float4& o, float& ss)
{
    float c, t;
    c = uv.x + sw.x; c = (c >= 0.f) ? c : a * c; t = fmaf(g, c, hh.x); o.x = t; ss = fmaf(t, t, ss);
    c = uv.y + sw.y; c = (c >= 0.f) ? c : a * c; t = fmaf(g, c, hh.y); o.y = t; ss = fmaf(t, t, ss);
    c = uv.z + sw.z; c = (c >= 0.f) ? c : a * c; t = fmaf(g, c, hh.z); o.z = t; ss = fmaf(t, t, ss);
    c = uv.w + sw.w; c = (c >= 0.f) ? c : a * c; t = fmaf(g, c, hh.w); o.w = t; ss = fmaf(t, t, ss);
}

__global__ void __launch_bounds__(256) k3q(
    const float* __restrict__ h, const float* __restrict__ a_ptr,
    float* __restrict__ out, const int bq)
{
    __shared__ float4 sw[2][64];
    __shared__ float gt[2][16];

    const int tid = threadIdx.x;
    const int warp = tid >> 5;
    const int lane = tid & 31;
    const int n0 = blockIdx.x * 16;
    const int b0 = bq * BQ_ + blockIdx.y * TB3;
    const float a = __ldg(a_ptr);

    const int nA = n0 + warp;
    const int nB = n0 + warp + 8;
    const int k0 = lane * 4;
    const int k1 = 128 + lane * 4;

    float4 uvA0 = *(const float4*)&g_UV[nA * H_ + k0];
    float4 uvA1 = *(const float4*)&g_UV[nA * H_ + k1];
    float4 uvB0 = *(const float4*)&g_UV[nB * H_ + k0];
    float4 uvB1 = *(const float4*)&g_UV[nB * H_ + k1];
    float4 hA0 = __ldg((const float4*)&h[nA * H_ + k0]);
    float4 hA1 = __ldg((const float4*)&h[nA * H_ + k1]);
    float4 hB0 = __ldg((const float4*)&h[nB * H_ + k0]);
    float4 hB1 = __ldg((const float4*)&h[nB * H_ + k1]);

    if (tid < 64) sw[0][tid] = __ldg((const float4*)&g_sW[(size_t)b0 * H_] + tid);
    else if (tid < 80) gt[0][tid - 64] = __ldg(&g_gate[b0 * N_ + n0 + (tid - 64)]);
    __syncthreads();

    for (int i = 0; i < TB3; ++i) {
        const int buf = i & 1;
        if (i + 1 < TB3) {
            const int bn = b0 + i + 1;
            if (tid < 64) sw[buf ^ 1][tid] = __ldg((const float4*)&g_sW[(size_t)bn * H_] + tid);
            else if (tid < 80) gt[buf ^ 1][tid - 64] = __ldg(&g_gate[bn * N_ + n0 + (tid - 64)]);
        }

        const float4 s0 = sw[buf][lane];
        const float4 s1 = sw[buf][lane + 32];
        const float gA = gt[buf][warp];
        const float gB = gt[buf][warp + 8];

        float4 oA0, oA1, oB0, oB1;
        float ssA = 0.f, ssB = 0.f;
        row_step(uvA0, hA0, s0, gA, a, oA0, ssA);
        row_step(uvA1, hA1, s1, gA, a, oA1, ssA);
        row_step(uvB0, hB0, s0, gB, a, oB0, ssB);
        row_step(uvB1, hB1, s1, gB, a, oB1, ssB);

#pragma unroll
        for (int offm = 16; offm > 0; offm >>= 1) {
            ssA += __shfl_xor_sync(0xFFFFFFFFu, ssA, offm);
            ssB += __shfl_xor_sync(0xFFFFFFFFu, ssB, offm);
        }
        const float iA = rsqrtf(ssA);
        const float iB = rsqrtf(ssB);

        const int b = b0 + i;
        float4* oA = (float4*)&out[((size_t)b * N_ + nA) * H_];
        float4* oB = (float4*)&out[((size_t)b * N_ + nB) * H_];
        oA[lane]      = make_float4(oA0.x * iA, oA0.y * iA, oA0.z * iA, oA0.w * iA);
        oA[32 + lane] = make_float4(oA1.x * iA, oA1.y * iA, oA1.z * iA, oA1.w * iA);
        oB[lane]      = make_float4(oB0.x * iB, oB0.y * iB, oB0.z * iB, oB0.w * iB);
        oB[32 + lane] = make_float4(oB1.x * iB, oB1.y * iB, oB1.z * iB, oB1.w * iB);

        __syncthreads();
    }
}

// ---------------------------------------------------------------------------
// Pipelined launch: producer quarters on the main (capture) stream, consumer
// quarters on a forked stream connected via event edges. Streams/events are
// created on the first call (which is the non-captured correctness call);
// every call enqueues identical work.
// ---------------------------------------------------------------------------
extern "C" void kernel_launch(void* const* d_in, const int* in_sizes, int n_in,
                              void* d_out, int out_size)
{
    const float* s_t = (const float*)d_in[0];   // [B,H]
    const float* h   = (const float*)d_in[1];   // [1,N,H]
    const float* w   = (const float*)d_in[2];   // [1,N,H]
    const float* U   = (const float*)d_in[3];   // [H,H]
    const float* V   = (const float*)d_in[4];   // [H,H]
    const float* W   = (const float*)d_in[5];   // [H,H]
    const float* pa  = (const float*)d_in[6];   // [1]
    float* out = (float*)d_out;                 // [B,N,H]

    static cudaStream_t s2 = nullptr;
    static cudaEvent_t eg[4];
    static cudaEvent_t ek;
    if (s2 == nullptr) {
        cudaStreamCreateWithFlags(&s2, cudaStreamNonBlocking);
        for (int q = 0; q < 4; ++q)
            cudaEventCreateWithFlags(&eg[q], cudaEventDisableTiming);
        cudaEventCreateWithFlags(&ek, cudaEventDisableTiming);
    }

    // Producers on the main stream; record an event after each quarter.
    for (int q = 0; q < 4; ++q) {
        const int grid = (q == 0) ? (NB_GQ + NB_UV) : NB_GQ;
        k12q<<<grid, 256>>>(s_t, W, h, w, U, V, q);
        cudaEventRecord(eg[q], 0);
    }

    // Consumers on the forked stream, each gated on its producer quarter.
    dim3 g3(N_ / 16, BQ_ / TB3);
    for (int q = 0; q < 4; ++q) {
        cudaStreamWaitEvent(s2, eg[q], 0);
        k3q<<<g3, 256, 0, s2>>>(h, pa, out, q);
    }
    cudaEventRecord(ek, s2);
    cudaStreamWaitEvent(0, ek, 0);   // join fork back into the main stream
}

// round 8
// speedup vs baseline: 1.9568x; 1.9568x over previous
#include <cuda_runtime.h>

#define B_ 4096
#define N_ 64
#define H_ 256
#define TB3 16

#define NB_GEMM 640   // 64 b-tiles x 5 m-tiles x 2 K-splits (64x64 tiles, K=128 each)
#define NB_UV   2048

typedef unsigned long long u64;

// Scratch (allocation-free rule: __device__ globals)
__device__ float g_UV[N_ * H_];      //  64 KiB
__device__ float g_sW0[B_ * H_];     //   4 MiB  (K-split half 0)
__device__ float g_sW1[B_ * H_];     //   4 MiB  (K-split half 1)
__device__ float g_gl0[B_ * N_];     //   1 MiB  (gate logits half 0)
__device__ float g_gl1[B_ * N_];     //   1 MiB  (gate logits half 1)

// ---------- packed fp32x2 helpers (sm_103a FFMA2) ----------
__device__ __forceinline__ u64 pack2(float x, float y) {
    u64 r; asm("mov.b64 %0, {%1, %2};" : "=l"(r) : "f"(x), "f"(y)); return r;
}
__device__ __forceinline__ u64 fma2(u64 a, u64 b, u64 c) {
    u64 d; asm("fma.rn.f32x2 %0, %1, %2, %3;" : "=l"(d) : "l"(a), "l"(b), "l"(c)); return d;
}
__device__ __forceinline__ float2 unpack2(u64 v) {
    float2 r; asm("mov.b64 {%0, %1}, %2;" : "=f"(r.x), "=f"(r.y) : "l"(v)); return r;
}

// ---------------------------------------------------------------------------
// Merged kernel 1+2:
//  blocks [0,640):   split-K GEMM.  tile = blk>>1, ks = blk&1.
//    C_ks[b,m] = sum_{k in half ks} s_t[b,k] . M[m,k],  M = concat(W_w, h+w)
//    64x64 tile, K=128 per block (4 chunks of 32), k-major smem,
//    4b x 4m micro via f32x2 packed FMA.
//    m<256 -> g_sW{ks} ; gate tile (mx==4) -> g_gl{ks} (raw logits)
//  blocks [640, 2688): UV[n,k] = sum_h h[n,h]*U[k,h] + w[n,h]*V[k,h]
// ---------------------------------------------------------------------------
__global__ void __launch_bounds__(256) k12(
    const float* __restrict__ s, const float* __restrict__ W,
    const float* __restrict__ h, const float* __restrict__ w,
    const float* __restrict__ U, const float* __restrict__ V)
{
    __shared__ float sa[32][64];   // [k][b_local]
    __shared__ float sb[32][64];   // [k][m_local]
    const int tid = threadIdx.x;
    const int blk = blockIdx.x;

    if (blk < NB_GEMM) {
        const int tile = blk >> 1;
        const int ks = blk & 1;
        const int kbase = ks * 128;
        const int mx = tile % 5;
        const int b0 = (tile / 5) * 64;
        const int m0 = mx * 64;
        const bool gate_tile = (mx == 4);
        float* __restrict__ outW = ks ? g_sW1 : g_sW0;
        float* __restrict__ outG = ks ? g_gl1 : g_gl0;

        const int row = tid & 63;
        const int kq = (tid >> 6) << 2;    // 0,4,8,12
        const int tx = tid & 15;
        const int ty = tid >> 4;
        const int rb = ty << 2;            // b micro base (4 rows = 2 pairs)
        const int cm = tx << 2;            // m micro base (4 cols)

        u64 acc2[2][4] = {};

        float4 ra0, ra1, rb0, rb1;
        ra0 = *(const float4*)&s[(b0 + row) * H_ + kbase + kq];
        ra1 = *(const float4*)&s[(b0 + row) * H_ + kbase + 16 + kq];
        if (!gate_tile) {
            rb0 = *(const float4*)&W[(m0 + row) * H_ + kbase + kq];
            rb1 = *(const float4*)&W[(m0 + row) * H_ + kbase + 16 + kq];
        } else {
            float4 x0 = *(const float4*)&h[row * H_ + kbase + kq];
            float4 x1 = *(const float4*)&h[row * H_ + kbase + 16 + kq];
            float4 y0 = *(const float4*)&w[row * H_ + kbase + kq];
            float4 y1 = *(const float4*)&w[row * H_ + kbase + 16 + kq];
            rb0 = make_float4(x0.x + y0.x, x0.y + y0.y, x0.z + y0.z, x0.w + y0.w);
            rb1 = make_float4(x1.x + y1.x, x1.y + y1.y, x1.z + y1.z, x1.w + y1.w);
        }

        for (int kc = 0; kc < 128; kc += 32) {
            sa[kq + 0][row] = ra0.x; sa[kq + 1][row] = ra0.y;
            sa[kq + 2][row] = ra0.z; sa[kq + 3][row] = ra0.w;
            sa[16 + kq + 0][row] = ra1.x; sa[16 + kq + 1][row] = ra1.y;
            sa[16 + kq + 2][row] = ra1.z; sa[16 + kq + 3][row] = ra1.w;
            sb[kq + 0][row] = rb0.x; sb[kq + 1][row] = rb0.y;
            sb[kq + 2][row] = rb0.z; sb[kq + 3][row] = rb0.w;
            sb[16 + kq + 0][row] = rb1.x; sb[16 + kq + 1][row] = rb1.y;
            sb[16 + kq + 2][row] = rb1.z; sb[16 + kq + 3][row] = rb1.w;
            __syncthreads();

            if (kc + 32 < 128) {
                const int kn = kbase + kc + 32;
                ra0 = *(const float4*)&s[(b0 + row) * H_ + kn + kq];
                ra1 = *(const float4*)&s[(b0 + row) * H_ + kn + 16 + kq];
                if (!gate_tile) {
                    rb0 = *(const float4*)&W[(m0 + row) * H_ + kn + kq];
                    rb1 = *(const float4*)&W[(m0 + row) * H_ + kn + 16 + kq];
                } else {
                    float4 x0 = *(const float4*)&h[row * H_ + kn + kq];
                    float4 x1 = *(const float4*)&h[row * H_ + kn + 16 + kq];
                    float4 y0 = *(const float4*)&w[row * H_ + kn + kq];
                    float4 y1 = *(const float4*)&w[row * H_ + kn + 16 + kq];
                    rb0 = make_float4(x0.x + y0.x, x0.y + y0.y, x0.z + y0.z, x0.w + y0.w);
                    rb1 = make_float4(x1.x + y1.x, x1.y + y1.y, x1.z + y1.z, x1.w + y1.w);
                }
            }

#pragma unroll 8
            for (int k = 0; k < 32; ++k) {
                const ulonglong2 a2 = *(const ulonglong2*)&sa[k][rb];
                const float4 bv = *(const float4*)&sb[k][cm];
                u64 bx = pack2(bv.x, bv.x);
                u64 by = pack2(bv.y, bv.y);
                u64 bz = pack2(bv.z, bv.z);
                u64 bw = pack2(bv.w, bv.w);
                acc2[0][0] = fma2(a2.x, bx, acc2[0][0]);
                acc2[0][1] = fma2(a2.x, by, acc2[0][1]);
                acc2[0][2] = fma2(a2.x, bz, acc2[0][2]);
                acc2[0][3] = fma2(a2.x, bw, acc2[0][3]);
                acc2[1][0] = fma2(a2.y, bx, acc2[1][0]);
                acc2[1][1] = fma2(a2.y, by, acc2[1][1]);
                acc2[1][2] = fma2(a2.y, bz, acc2[1][2]);
                acc2[1][3] = fma2(a2.y, bw, acc2[1][3]);
            }
            __syncthreads();
        }

#pragma unroll
        for (int ib = 0; ib < 2; ++ib) {
            float2 c0 = unpack2(acc2[ib][0]);
            float2 c1 = unpack2(acc2[ib][1]);
            float2 c2 = unpack2(acc2[ib][2]);
            float2 c3 = unpack2(acc2[ib][3]);
            const int bA = b0 + rb + 2 * ib;
            if (!gate_tile) {
                *(float4*)&outW[bA * H_ + m0 + cm] = make_float4(c0.x, c1.x, c2.x, c3.x);
                *(float4*)&outW[(bA + 1) * H_ + m0 + cm] = make_float4(c0.y, c1.y, c2.y, c3.y);
            } else {
                *(float4*)&outG[bA * N_ + cm] = make_float4(c0.x, c1.x, c2.x, c3.x);
                *(float4*)&outG[(bA + 1) * N_ + cm] = make_float4(c0.y, c1.y, c2.y, c3.y);
            }
        }
    } else {
        // ---------------- UV part: warp per output element ----------------
        const int id = blk - NB_GEMM;
        const int n = id >> 5;
        const int kg = id & 31;
        const int warp = tid >> 5;
        const int lane = tid & 31;
        const int k = kg * 8 + warp;
        const int off = lane * 8;

        const float4* u4 = (const float4*)(U + k * H_ + off);
        const float4* v4 = (const float4*)(V + k * H_ + off);
        const float4* h4 = (const float4*)(h + n * H_ + off);
        const float4* w4 = (const float4*)(w + n * H_ + off);
        float4 u0 = u4[0], u1 = u4[1];
        float4 v0 = v4[0], v1 = v4[1];
        float4 x0 = __ldg(h4), x1 = __ldg(h4 + 1);
        float4 y0 = __ldg(w4), y1 = __ldg(w4 + 1);

        float acc = 0.f;
        acc = fmaf(u0.x, x0.x, acc); acc = fmaf(u0.y, x0.y, acc);
        acc = fmaf(u0.z, x0.z, acc); acc = fmaf(u0.w, x0.w, acc);
        acc = fmaf(u1.x, x1.x, acc); acc = fmaf(u1.y, x1.y, acc);
        acc = fmaf(u1.z, x1.z, acc); acc = fmaf(u1.w, x1.w, acc);
        acc = fmaf(v0.x, y0.x, acc); acc = fmaf(v0.y, y0.y, acc);
        acc = fmaf(v0.z, y0.z, acc); acc = fmaf(v0.w, y0.w, acc);
        acc = fmaf(v1.x, y1.x, acc); acc = fmaf(v1.y, y1.y, acc);
        acc = fmaf(v1.z, y1.z, acc); acc = fmaf(v1.w, y1.w, acc);

#pragma unroll
        for (int offm = 16; offm > 0; offm >>= 1)
            acc += __shfl_xor_sync(0xFFFFFFFFu, acc, offm);
        if (lane == 0) g_UV[n * H_ + k] = acc;
    }
}

// ---------------------------------------------------------------------------
// Kernel 3 (R2 body): out[b,n,:] = normalize(h[n,:] + g*prelu(UV + sW))
// sW = sW0+sW1 and gate = sigmoid(gl0+gl1), both fused into staging loads.
// grid = (4 n-tiles, B/TB3), block = 256 (warp w -> rows w, w+8)
// ---------------------------------------------------------------------------
__device__ __forceinline__ void row_step(const float4 uv, const float4 hh,
                                         const float4 sw, const float g,
                                         const float a, float4& o, float& ss)
{
    float c, t;
    c = uv.x + sw.x; c = (c >= 0.f) ? c : a * c; t = fmaf(g, c, hh.x); o.x = t; ss = fmaf(t, t, ss);
    c = uv.y + sw.y; c = (c >= 0.f) ? c : a * c; t = fmaf(g, c, hh.y); o.y = t; ss = fmaf(t, t, ss);
    c = uv.z + sw.z; c = (c >= 0.f) ? c : a * c; t = fmaf(g, c, hh.z); o.z = t; ss = fmaf(t, t, ss);
    c = uv.w + sw.w; c = (c >= 0.f) ? c : a * c; t = fmaf(g, c, hh.w); o.w = t; ss = fmaf(t, t, ss);
}

__global__ void __launch_bounds__(256) k3_main(
    const float* __restrict__ h, const float* __restrict__ a_ptr,
    float* __restrict__ out)
{
    __shared__ float4 sw[2][64];
    __shared__ float gt[2][16];

    const int tid = threadIdx.x;
    const int warp = tid >> 5;
    const int lane = tid & 31;
    const int n0 = blockIdx.x * 16;
    const int b0 = blockIdx.y * TB3;
    const float a = __ldg(a_ptr);

    const int nA = n0 + warp;
    const int nB = n0 + warp + 8;
    const int k0 = lane * 4;
    const int k1 = 128 + lane * 4;

    float4 uvA0 = *(const float4*)&g_UV[nA * H_ + k0];
    float4 uvA1 = *(const float4*)&g_UV[nA * H_ + k1];
    float4 uvB0 = *(const float4*)&g_UV[nB * H_ + k0];
    float4 uvB1 = *(const float4*)&g_UV[nB * H_ + k1];
    float4 hA0 = __ldg((const float4*)&h[nA * H_ + k0]);
    float4 hA1 = __ldg((const float4*)&h[nA * H_ + k1]);
    float4 hB0 = __ldg((const float4*)&h[nB * H_ + k0]);
    float4 hB1 = __ldg((const float4*)&h[nB * H_ + k1]);

    if (tid < 64) {
        float4 p = __ldg((const float4*)&g_sW0[(size_t)b0 * H_] + tid);
        float4 q = __ldg((const float4*)&g_sW1[(size_t)b0 * H_] + tid);
        sw[0][tid] = make_float4(p.x + q.x, p.y + q.y, p.z + q.z, p.w + q.w);
    } else if (tid < 80) {
        const int j = b0 * N_ + n0 + (tid - 64);
        gt[0][tid - 64] = 1.0f / (1.0f + __expf(-(__ldg(&g_gl0[j]) + __ldg(&g_gl1[j]))));
    }
    __syncthreads();

    for (int i = 0; i < TB3; ++i) {
        const int buf = i & 1;
        if (i + 1 < TB3) {
            const int bn = b0 + i + 1;
            if (tid < 64) {
                float4 p = __ldg((const float4*)&g_sW0[(size_t)bn * H_] + tid);
                float4 q = __ldg((const float4*)&g_sW1[(size_t)bn * H_] + tid);
                sw[buf ^ 1][tid] = make_float4(p.x + q.x, p.y + q.y, p.z + q.z, p.w + q.w);
            } else if (tid < 80) {
                const int j = bn * N_ + n0 + (tid - 64);
                gt[buf ^ 1][tid - 64] = 1.0f / (1.0f + __expf(-(__ldg(&g_gl0[j]) + __ldg(&g_gl1[j]))));
            }
        }

        const float4 s0 = sw[buf][lane];
        const float4 s1 = sw[buf][lane + 32];
        const float gA = gt[buf][warp];
        const float gB = gt[buf][warp + 8];

        float4 oA0, oA1, oB0, oB1;
        float ssA = 0.f, ssB = 0.f;
        row_step(uvA0, hA0, s0, gA, a, oA0, ssA);
        row_step(uvA1, hA1, s1, gA, a, oA1, ssA);
        row_step(uvB0, hB0, s0, gB, a, oB0, ssB);
        row_step(uvB1, hB1, s1, gB, a, oB1, ssB);

#pragma unroll
        for (int offm = 16; offm > 0; offm >>= 1) {
            ssA += __shfl_xor_sync(0xFFFFFFFFu, ssA, offm);
            ssB += __shfl_xor_sync(0xFFFFFFFFu, ssB, offm);
        }
        const float iA = rsqrtf(ssA);
        const float iB = rsqrtf(ssB);

        const int b = b0 + i;
        float4* oA = (float4*)&out[((size_t)b * N_ + nA) * H_];
        float4* oB = (float4*)&out[((size_t)b * N_ + nB) * H_];
        oA[lane]      = make_float4(oA0.x * iA, oA0.y * iA, oA0.z * iA, oA0.w * iA);
        oA[32 + lane] = make_float4(oA1.x * iA, oA1.y * iA, oA1.z * iA, oA1.w * iA);
        oB[lane]      = make_float4(oB0.x * iB, oB0.y * iB, oB0.z * iB, oB0.w * iB);
        oB[32 + lane] = make_float4(oB1.x * iB, oB1.y * iB, oB1.z * iB, oB1.w * iB);

        __syncthreads();
    }
}

// ---------------------------------------------------------------------------
extern "C" void kernel_launch(void* const* d_in, const int* in_sizes, int n_in,
                              void* d_out, int out_size)
{
    const float* s_t = (const float*)d_in[0];   // [B,H]
    const float* h   = (const float*)d_in[1];   // [1,N,H]
    const float* w   = (const float*)d_in[2];   // [1,N,H]
    const float* U   = (const float*)d_in[3];   // [H,H]
    const float* V   = (const float*)d_in[4];   // [H,H]
    const float* W   = (const float*)d_in[5];   // [H,H]
    const float* pa  = (const float*)d_in[6];   // [1]
    float* out = (float*)d_out;                 // [B,N,H]

    k12<<<NB_GEMM + NB_UV, 256>>>(s_t, W, h, w, U, V);

    dim3 g3(N_ / 16, B_ / TB3);
    k3_main<<<g3, 256>>>(h, pa, out);
}